// round 11
// baseline (speedup 1.0000x reference)
#include <cuda_runtime.h>
#include <cstdint>

// Haar DWT2 on x:[8,64,512,512] f32 -> 4 subbands [8,64,256,256] packed
// subband-major into d_out (LL, LH, HL, HH).
//
// Round 10: last deconfounded cell in the matrix — WIDE STORES (STG.128)
// with plain cache ops at the best block size (1024). R2 tested wide stores
// only together with __ldcs/__stcs at BLOCK=256 (both since shown
// irrelevant/negative). Also extends the per-CTA footprint axis
// (monotonically positive so far) to 256 KiB.
//
// Each thread: 4 output columns of one output row.
//   reads  2x float4 from input row 2i, 2x from row 2i+1  (64 B)
//   writes 1x float4 to each of 4 subbands                 (64 B)

static constexpr int W_IN = 512;
static constexpr int H_OUT = 256;
static constexpr int W_OUT = 256;
static constexpr int QUADS_PER_ROW = W_OUT / 4;                  // 64 threads per output row
static constexpr long long PLANE_IN  = (long long)W_IN * W_IN;   // 262144
static constexpr long long PLANE_OUT = (long long)H_OUT * W_OUT; // 65536
static constexpr long long SUBBAND_STRIDE = 512LL * PLANE_OUT;   // 33,554,432

static constexpr unsigned BLOCK = 1024;

__device__ __forceinline__ void haar_pair(float a, float b, float c, float d,
                                          float& ll, float& lh, float& hl, float& hh)
{
    const float apb = a + b, amb = a - b;
    const float cpd = c + d, cmd = c - d;
    ll = (apb + cpd) * 0.5f;
    lh = (apb - cpd) * 0.5f;
    hl = (amb + cmd) * 0.5f;
    hh = (amb - cmd) * 0.5f;
}

__global__ void __launch_bounds__(BLOCK)
haar_dwt2_kernel(const float* __restrict__ x, float* __restrict__ out)
{
    const unsigned tid = blockIdx.x * BLOCK + threadIdx.x;
    // tid layout: [plane p : 512][out-row i : 256][col-quad j : 64]
    const unsigned j = tid & (QUADS_PER_ROW - 1);        // 0..63  (4 out cols = 8 in cols)
    const unsigned i = (tid >> 6) & (H_OUT - 1);         // 0..255
    const unsigned p = tid >> 14;                        // 0..511

    const float4* row0 = (const float4*)(x + (long long)p * PLANE_IN
                                           + (long long)(2u * i) * W_IN) + 2u * j;
    const float4* row1 = row0 + (W_IN / 4);

    const float4 r0a = __ldg(row0);
    const float4 r0b = __ldg(row0 + 1);
    const float4 r1a = __ldg(row1);
    const float4 r1b = __ldg(row1 + 1);

    float4 ll, lh, hl, hh;
    haar_pair(r0a.x, r0a.y, r1a.x, r1a.y, ll.x, lh.x, hl.x, hh.x);
    haar_pair(r0a.z, r0a.w, r1a.z, r1a.w, ll.y, lh.y, hl.y, hh.y);
    haar_pair(r0b.x, r0b.y, r1b.x, r1b.y, ll.z, lh.z, hl.z, hh.z);
    haar_pair(r0b.z, r0b.w, r1b.z, r1b.w, ll.w, lh.w, hl.w, hh.w);

    const long long obase = (long long)p * PLANE_OUT + (long long)i * W_OUT + 4u * j;
    *(float4*)(out + obase)                      = ll;
    *(float4*)(out + obase +     SUBBAND_STRIDE) = lh;
    *(float4*)(out + obase + 2 * SUBBAND_STRIDE) = hl;
    *(float4*)(out + obase + 3 * SUBBAND_STRIDE) = hh;
}

extern "C" void kernel_launch(void* const* d_in, const int* in_sizes, int n_in,
                              void* d_out, int out_size)
{
    const float* x = (const float*)d_in[0];
    float* out = (float*)d_out;

    // total threads = 512 planes * 256 rows * 64 quads = 8,388,608
    const unsigned total = 512u * 256u * 64u;
    const unsigned grid = total / BLOCK; // 8192
    haar_dwt2_kernel<<<grid, BLOCK>>>(x, out);
}

// round 12
// speedup vs baseline: 1.0160x; 1.0160x over previous
#include <cuda_runtime.h>
#include <cstdint>

// Haar DWT2 on x:[8,64,512,512] f32 -> 4 subbands [8,64,256,256] packed
// subband-major into d_out (LL, LH, HL, HH).
//
// FINAL (confirmed winner, measured 154.1us / 154.7us across two runs):
// BLOCK=1024, plain __ldg float4 loads, plain float2 stores.
// DRAM=86.3-86.6%, HBM=6838-6860 GB/s (85.5-85.8% of 8 TB/s spec) — the
// mixed 1:1 read/write HBM3e ceiling. Traffic is compulsory-minimal (1 GiB).
// Exhausted axes (all neutral or worse): load/store width (R2/R10),
// ldcs/stcs cache policy (R2/R8), persistent grid + prefetch (R3),
// CTA size 256/512/1024 (R1/R6/R7; 1024 best), footprint >128KiB (R10).
//
// Each thread: 2 output columns of one output row.
//   reads  float4 from input rows 2i and 2i+1  (32 B)
//   writes float2 to each of 4 subbands        (32 B)

static constexpr int W_IN = 512;
static constexpr int H_OUT = 256;
static constexpr int W_OUT = 256;
static constexpr int PAIRS_PER_ROW = W_OUT / 2;                  // 128 threads per output row
static constexpr long long PLANE_IN  = (long long)W_IN * W_IN;   // 262144
static constexpr long long PLANE_OUT = (long long)H_OUT * W_OUT; // 65536
static constexpr long long SUBBAND_STRIDE = 512LL * PLANE_OUT;   // 33,554,432

static constexpr unsigned BLOCK = 1024;

__global__ void __launch_bounds__(BLOCK)
haar_dwt2_kernel(const float* __restrict__ x, float* __restrict__ out)
{
    const unsigned tid = blockIdx.x * BLOCK + threadIdx.x;
    // tid layout: [plane p : 512][out-row i : 256][col-pair j2 : 128]
    const unsigned j2 = tid & (PAIRS_PER_ROW - 1);       // 0..127
    const unsigned i  = (tid >> 7) & (H_OUT - 1);        // 0..255
    const unsigned p  = tid >> 15;                       // 0..511

    const float* base = x + (long long)p * PLANE_IN + (long long)(2u * i) * W_IN;
    const float4 r0 = __ldg((const float4*)base + j2);              // row 2i
    const float4 r1 = __ldg((const float4*)base + (W_IN / 4) + j2); // row 2i+1

    const float s = 0.5f;

    float2 ll, lh, hl, hh;
    {
        const float apb = r0.x + r0.y, amb = r0.x - r0.y;
        const float cpd = r1.x + r1.y, cmd = r1.x - r1.y;
        ll.x = (apb + cpd) * s;
        lh.x = (apb - cpd) * s;
        hl.x = (amb + cmd) * s;
        hh.x = (amb - cmd) * s;
    }
    {
        const float apb = r0.z + r0.w, amb = r0.z - r0.w;
        const float cpd = r1.z + r1.w, cmd = r1.z - r1.w;
        ll.y = (apb + cpd) * s;
        lh.y = (apb - cpd) * s;
        hl.y = (amb + cmd) * s;
        hh.y = (amb - cmd) * s;
    }

    const long long obase = (long long)p * PLANE_OUT + (long long)i * W_OUT + 2u * j2;
    *(float2*)(out + obase)                      = ll;
    *(float2*)(out + obase +     SUBBAND_STRIDE) = lh;
    *(float2*)(out + obase + 2 * SUBBAND_STRIDE) = hl;
    *(float2*)(out + obase + 3 * SUBBAND_STRIDE) = hh;
}

extern "C" void kernel_launch(void* const* d_in, const int* in_sizes, int n_in,
                              void* d_out, int out_size)
{
    const float* x = (const float*)d_in[0];
    float* out = (float*)d_out;

    // total threads = 512 planes * 256 rows * 128 pairs = 16,777,216
    const unsigned total = 512u * 256u * 128u;
    const unsigned grid = total / BLOCK; // 16384
    haar_dwt2_kernel<<<grid, BLOCK>>>(x, out);
}

// round 13
// speedup vs baseline: 1.0240x; 1.0079x over previous
#include <cuda_runtime.h>
#include <cstdint>

// Haar DWT2 on x:[8,64,512,512] f32 -> 4 subbands [8,64,256,256] packed
// subband-major into d_out (LL, LH, HL, HH).
//
// FINAL — converged winner, measured 3x: wall 154.1/154.7/156.0 us,
// ncu kernel time 149.4/149.7/149.2 us (stable), DRAM 86.3-86.6%,
// HBM 6838-6860 GB/s (85.5-85.8% of 8 TB/s spec) = the mixed 1:1
// read/write HBM3e ceiling on this part. Traffic is compulsory-minimal
// (1 GiB); SM side idle (issue 18%, regs 20, no spills).
//
// Exhausted axes (all neutral or worse across 7 structural variants):
//   - load/store width LDG.128/STG.64 vs wider (R2, R10)
//   - cache policy __ldcs/__stcs, tested separately (R2, R8)
//   - persistent grid + cross-iteration prefetch (R3)
//   - CTA size 256/512/1024 (R1/R6/R7; 1024 best, -1.3%)
//   - per-CTA footprint beyond 128 KiB (R10, worse)
//
// Each thread: 2 output columns of one output row.
//   reads  float4 from input rows 2i and 2i+1  (32 B)
//   writes float2 to each of 4 subbands        (32 B)

static constexpr int W_IN = 512;
static constexpr int H_OUT = 256;
static constexpr int W_OUT = 256;
static constexpr int PAIRS_PER_ROW = W_OUT / 2;                  // 128 threads per output row
static constexpr long long PLANE_IN  = (long long)W_IN * W_IN;   // 262144
static constexpr long long PLANE_OUT = (long long)H_OUT * W_OUT; // 65536
static constexpr long long SUBBAND_STRIDE = 512LL * PLANE_OUT;   // 33,554,432

static constexpr unsigned BLOCK = 1024;

__global__ void __launch_bounds__(BLOCK)
haar_dwt2_kernel(const float* __restrict__ x, float* __restrict__ out)
{
    const unsigned tid = blockIdx.x * BLOCK + threadIdx.x;
    // tid layout: [plane p : 512][out-row i : 256][col-pair j2 : 128]
    const unsigned j2 = tid & (PAIRS_PER_ROW - 1);       // 0..127
    const unsigned i  = (tid >> 7) & (H_OUT - 1);        // 0..255
    const unsigned p  = tid >> 15;                       // 0..511

    const float* base = x + (long long)p * PLANE_IN + (long long)(2u * i) * W_IN;
    const float4 r0 = __ldg((const float4*)base + j2);              // row 2i
    const float4 r1 = __ldg((const float4*)base + (W_IN / 4) + j2); // row 2i+1

    const float s = 0.5f;

    float2 ll, lh, hl, hh;
    {
        const float apb = r0.x + r0.y, amb = r0.x - r0.y;
        const float cpd = r1.x + r1.y, cmd = r1.x - r1.y;
        ll.x = (apb + cpd) * s;
        lh.x = (apb - cpd) * s;
        hl.x = (amb + cmd) * s;
        hh.x = (amb - cmd) * s;
    }
    {
        const float apb = r0.z + r0.w, amb = r0.z - r0.w;
        const float cpd = r1.z + r1.w, cmd = r1.z - r1.w;
        ll.y = (apb + cpd) * s;
        lh.y = (apb - cpd) * s;
        hl.y = (amb + cmd) * s;
        hh.y = (amb - cmd) * s;
    }

    const long long obase = (long long)p * PLANE_OUT + (long long)i * W_OUT + 2u * j2;
    *(float2*)(out + obase)                      = ll;
    *(float2*)(out + obase +     SUBBAND_STRIDE) = lh;
    *(float2*)(out + obase + 2 * SUBBAND_STRIDE) = hl;
    *(float2*)(out + obase + 3 * SUBBAND_STRIDE) = hh;
}

extern "C" void kernel_launch(void* const* d_in, const int* in_sizes, int n_in,
                              void* d_out, int out_size)
{
    const float* x = (const float*)d_in[0];
    float* out = (float*)d_out;

    // total threads = 512 planes * 256 rows * 128 pairs = 16,777,216
    const unsigned total = 512u * 256u * 128u;
    const unsigned grid = total / BLOCK; // 16384
    haar_dwt2_kernel<<<grid, BLOCK>>>(x, out);
}

// round 14
// speedup vs baseline: 1.0285x; 1.0044x over previous
#include <cuda_runtime.h>
#include <cstdint>

// Haar DWT2 on x:[8,64,512,512] f32 -> 4 subbands [8,64,256,256] packed
// subband-major into d_out (LL, LH, HL, HH).
//
// FINAL — converged winner, measured 4x:
//   wall 154.1 / 154.7 / 156.0 / 154.8 us
//   ncu kernel 149.4 / 149.7 / 149.2 / 149.6 us  (0.3% band)
//   DRAM 86.3-86.6%, HBM 6838-6860 GB/s (85.5-85.8% of 8 TB/s spec)
// = the mixed 1:1 read/write HBM3e ceiling on this part. Traffic is
// compulsory-minimal (1 GiB); SM side idle (issue 18%, regs 20, no spills).
// 1 GiB / 6.85 TB/s ~= 157us serialized vs 149.6us measured => read/write
// streams already overlap at the controller; no hidden slack.
//
// Exhausted axes (all neutral or worse across 7 structural variants):
//   - load/store width (R2, R10)          - cache policy ldcs/stcs (R2, R8)
//   - persistent grid + prefetch (R3)     - CTA 256/512/1024 (1024 best, -1.3%)
//   - per-CTA footprint >128 KiB (R10)    - TMA ruled out by HW data
//     (B300_MICROARCH: LTS cap is path-independent, LDG.cv == TMA)
//
// Each thread: 2 output columns of one output row.
//   reads  float4 from input rows 2i and 2i+1  (32 B)
//   writes float2 to each of 4 subbands        (32 B)

static constexpr int W_IN = 512;
static constexpr int H_OUT = 256;
static constexpr int W_OUT = 256;
static constexpr int PAIRS_PER_ROW = W_OUT / 2;                  // 128 threads per output row
static constexpr long long PLANE_IN  = (long long)W_IN * W_IN;   // 262144
static constexpr long long PLANE_OUT = (long long)H_OUT * W_OUT; // 65536
static constexpr long long SUBBAND_STRIDE = 512LL * PLANE_OUT;   // 33,554,432

static constexpr unsigned BLOCK = 1024;

__global__ void __launch_bounds__(BLOCK)
haar_dwt2_kernel(const float* __restrict__ x, float* __restrict__ out)
{
    const unsigned tid = blockIdx.x * BLOCK + threadIdx.x;
    // tid layout: [plane p : 512][out-row i : 256][col-pair j2 : 128]
    const unsigned j2 = tid & (PAIRS_PER_ROW - 1);       // 0..127
    const unsigned i  = (tid >> 7) & (H_OUT - 1);        // 0..255
    const unsigned p  = tid >> 15;                       // 0..511

    const float* base = x + (long long)p * PLANE_IN + (long long)(2u * i) * W_IN;
    const float4 r0 = __ldg((const float4*)base + j2);              // row 2i
    const float4 r1 = __ldg((const float4*)base + (W_IN / 4) + j2); // row 2i+1

    const float s = 0.5f;

    float2 ll, lh, hl, hh;
    {
        const float apb = r0.x + r0.y, amb = r0.x - r0.y;
        const float cpd = r1.x + r1.y, cmd = r1.x - r1.y;
        ll.x = (apb + cpd) * s;
        lh.x = (apb - cpd) * s;
        hl.x = (amb + cmd) * s;
        hh.x = (amb - cmd) * s;
    }
    {
        const float apb = r0.z + r0.w, amb = r0.z - r0.w;
        const float cpd = r1.z + r1.w, cmd = r1.z - r1.w;
        ll.y = (apb + cpd) * s;
        lh.y = (apb - cpd) * s;
        hl.y = (amb + cmd) * s;
        hh.y = (amb - cmd) * s;
    }

    const long long obase = (long long)p * PLANE_OUT + (long long)i * W_OUT + 2u * j2;
    *(float2*)(out + obase)                      = ll;
    *(float2*)(out + obase +     SUBBAND_STRIDE) = lh;
    *(float2*)(out + obase + 2 * SUBBAND_STRIDE) = hl;
    *(float2*)(out + obase + 3 * SUBBAND_STRIDE) = hh;
}

extern "C" void kernel_launch(void* const* d_in, const int* in_sizes, int n_in,
                              void* d_out, int out_size)
{
    const float* x = (const float*)d_in[0];
    float* out = (float*)d_out;

    // total threads = 512 planes * 256 rows * 128 pairs = 16,777,216
    const unsigned total = 512u * 256u * 128u;
    const unsigned grid = total / BLOCK; // 16384
    haar_dwt2_kernel<<<grid, BLOCK>>>(x, out);
}